// round 2
// baseline (speedup 1.0000x reference)
#include <cuda_runtime.h>
#include <math.h>

#define BB 16
#define CC 512
#define TT 1024     // h*w
#define NH 8
#define HD 64
#define NG 32
#define CPG 16      // channels per group

// Scratch (allocation-free rule: __device__ globals)
__device__ float g_xn[BB * CC * TT];          // 33.5 MB
__device__ float g_qkv[BB * 3 * CC * TT];     // 100 MB
__device__ float g_att[BB * CC * TT];         // 33.5 MB

// ---------------------------------------------------------------------------
// GroupNorm: one block per (b, group). Two passes over 16*1024 floats.
// ---------------------------------------------------------------------------
__global__ void gn_kernel(const float* __restrict__ x,
                          const float* __restrict__ gamma,
                          const float* __restrict__ beta) {
    int b = blockIdx.x >> 5;
    int g = blockIdx.x & 31;
    const float* xb = x + ((size_t)b * CC + (size_t)g * CPG) * TT;
    float* ob = g_xn + ((size_t)b * CC + (size_t)g * CPG) * TT;
    int tid = threadIdx.x;

    float s = 0.f, ss = 0.f;
    for (int i = tid; i < CPG * TT; i += 256) {
        float v = xb[i];
        s += v;
        ss += v * v;
    }
    __shared__ float rs[8], rss[8];
    #pragma unroll
    for (int o = 16; o > 0; o >>= 1) {
        s  += __shfl_down_sync(0xffffffff, s, o);
        ss += __shfl_down_sync(0xffffffff, ss, o);
    }
    if ((tid & 31) == 0) { rs[tid >> 5] = s; rss[tid >> 5] = ss; }
    __syncthreads();
    __shared__ float s_mean, s_inv;
    if (tid == 0) {
        float S = 0.f, SS = 0.f;
        #pragma unroll
        for (int i = 0; i < 8; i++) { S += rs[i]; SS += rss[i]; }
        float mean = S * (1.f / (CPG * TT));
        float var = SS * (1.f / (CPG * TT)) - mean * mean;
        s_mean = mean;
        s_inv = rsqrtf(var + 1e-5f);
    }
    __syncthreads();
    float mean = s_mean, inv = s_inv;
    for (int i = tid; i < CPG * TT; i += 256) {
        int c = i >> 10;               // /TT
        int ch = g * CPG + c;
        ob[i] = (xb[i] - mean) * inv * gamma[ch] + beta[ch];
    }
}

// ---------------------------------------------------------------------------
// SIMT SGEMM: C[b][m][n] = sum_k A[m][k]*Bm[b][k][n] + bias[m] (+ resid)
// BM=BN=64, BK=16, 256 threads, 4x4 per thread. N fixed = TT, K multiple of 16.
// ---------------------------------------------------------------------------
__global__ void gemm_bias_kernel(const float* __restrict__ A,     // [M,K]
                                 const float* __restrict__ Bm,    // [b][K,TT]
                                 const float* __restrict__ bias,  // [M]
                                 const float* __restrict__ resid, // [b][M,TT] or null
                                 float* __restrict__ Cm,          // [b][M,TT]
                                 int M, int K) {
    const int N = TT;
    int bb = blockIdx.z;
    int m0 = blockIdx.y * 64;
    int n0 = blockIdx.x * 64;
    const float* Bb = Bm + (size_t)bb * K * N;
    float* Cb = Cm + (size_t)bb * (size_t)M * N;
    const float* Rb = resid ? resid + (size_t)bb * (size_t)M * N : nullptr;

    __shared__ float As[16][64];   // [k][m]
    __shared__ float Bs[16][64];   // [k][n]

    int tid = threadIdx.x;
    int tx = tid & 15, ty = tid >> 4;

    int arow  = tid >> 2;          // 0..63
    int acol4 = (tid & 3) * 4;     // 0..12
    int brow  = tid >> 4;          // 0..15
    int bcol4 = (tid & 15) * 4;    // 0..60

    float acc[4][4] = {};

    for (int k0 = 0; k0 < K; k0 += 16) {
        float4 av = *(const float4*)&A[(size_t)(m0 + arow) * K + k0 + acol4];
        float4 bv = *(const float4*)&Bb[(size_t)(k0 + brow) * N + n0 + bcol4];
        __syncthreads();
        As[acol4 + 0][arow] = av.x;
        As[acol4 + 1][arow] = av.y;
        As[acol4 + 2][arow] = av.z;
        As[acol4 + 3][arow] = av.w;
        *(float4*)&Bs[brow][bcol4] = bv;
        __syncthreads();
        #pragma unroll
        for (int k = 0; k < 16; k++) {
            float a[4], bvv[4];
            *(float4*)a   = *(const float4*)&As[k][ty * 4];
            *(float4*)bvv = *(const float4*)&Bs[k][tx * 4];
            #pragma unroll
            for (int i = 0; i < 4; i++)
                #pragma unroll
                for (int j = 0; j < 4; j++)
                    acc[i][j] += a[i] * bvv[j];
        }
    }

    #pragma unroll
    for (int i = 0; i < 4; i++) {
        int m = m0 + ty * 4 + i;
        float bi = bias[m];
        #pragma unroll
        for (int j = 0; j < 4; j++) {
            int n = n0 + tx * 4 + j;
            float v = acc[i][j] + bi;
            if (Rb) v += Rb[(size_t)m * N + n];
            Cb[(size_t)m * N + n] = v;
        }
    }
}

// ---------------------------------------------------------------------------
// Flash-style attention: block = (64-query tile, head, batch), 256 threads.
// Streams K/V in 64-key chunks; online softmax; O in registers.
// smem: Qs[64][64] + KVs[64][65] + Ps[64][65] + m/l/rsc[64 each]
// ---------------------------------------------------------------------------
#define ATTN_SMEM_FLOATS (4096 + 4160 + 4160 + 192)
#define ATTN_SMEM_BYTES (ATTN_SMEM_FLOATS * 4)

__global__ void attn_kernel() {
    extern __shared__ float sm[];
    float* Qs  = sm;                 // [d][i] pitch 64
    float* KVs = sm + 4096;          // K: [d][j] pitch 65 ; V: [j][d] pitch 65
    float* Ps  = KVs + 4160;         // [j][i] pitch 65
    float* mrow = Ps + 4160;         // [64]
    float* lrow = mrow + 64;         // [64]
    float* rsc  = lrow + 64;         // [64]

    int qt = blockIdx.x, hh = blockIdx.y, bb = blockIdx.z;
    int i0 = qt * 64;
    const float* qb = g_qkv + ((size_t)bb * 3 * CC + (size_t)hh * HD) * TT;
    const float* kb = qb + (size_t)CC * TT;
    const float* vb = kb + (size_t)CC * TT;

    int tid = threadIdx.x;
    int tx = tid & 15, ty = tid >> 4;

    for (int l = tid; l < 4096; l += 256) {
        int d = l >> 6, i = l & 63;
        Qs[d * 64 + i] = qb[(size_t)d * TT + i0 + i];
    }
    if (tid < 64) { mrow[tid] = -INFINITY; lrow[tid] = 0.f; }

    float acc[4][4] = {};
    const float scale = 0.125f;      // 1/sqrt(64)

    for (int kt = 0; kt < 16; kt++) {
        int j0 = kt * 64;
        __syncthreads();             // prev iter done with KVs/Ps; Q ready (iter 0)
        for (int l = tid; l < 4096; l += 256) {
            int d = l >> 6, j = l & 63;
            KVs[d * 65 + j] = kb[(size_t)d * TT + j0 + j];
        }
        __syncthreads();

        // S = (Q K^T) * scale, 4x4 register tile per thread
        float s[4][4] = {};
        #pragma unroll
        for (int d = 0; d < 64; d++) {
            float qv[4], kv[4];
            #pragma unroll
            for (int r = 0; r < 4; r++) qv[r] = Qs[d * 64 + ty * 4 + r];
            #pragma unroll
            for (int c = 0; c < 4; c++) kv[c] = KVs[d * 65 + tx * 4 + c];
            #pragma unroll
            for (int r = 0; r < 4; r++)
                #pragma unroll
                for (int c = 0; c < 4; c++)
                    s[r][c] += qv[r] * kv[c];
        }
        #pragma unroll
        for (int r = 0; r < 4; r++)
            #pragma unroll
            for (int c = 0; c < 4; c++)
                Ps[(tx * 4 + c) * 65 + ty * 4 + r] = s[r][c] * scale;
        __syncthreads();             // S done reading K; Ps complete

        // warps 0-1: online softmax per query row | warps 2-7: load V over K
        if (tid < 64) {
            int i = tid;
            float m = mrow[i];
            float nm = m;
            #pragma unroll 8
            for (int j = 0; j < 64; j++) nm = fmaxf(nm, Ps[j * 65 + i]);
            float rs_ = __expf(m - nm);
            float li = lrow[i] * rs_;
            #pragma unroll 8
            for (int j = 0; j < 64; j++) {
                float p = __expf(Ps[j * 65 + i] - nm);
                Ps[j * 65 + i] = p;
                li += p;
            }
            mrow[i] = nm;
            lrow[i] = li;
            rsc[i] = rs_;
        } else {
            int t2 = tid - 64;
            for (int l = t2; l < 4096; l += 192) {
                int d = l >> 6, j = l & 63;
                KVs[j * 65 + d] = vb[(size_t)d * TT + j0 + j];  // V as [j][d]
            }
        }
        __syncthreads();

        // rescale accumulator
        #pragma unroll
        for (int r = 0; r < 4; r++) {
            float sc = rsc[ty * 4 + r];
            #pragma unroll
            for (int c = 0; c < 4; c++) acc[r][c] *= sc;
        }
        // O[i][d] += sum_j P[i][j] * V[j][d]   (i = ty*4+r, d = tx*4+c)
        #pragma unroll
        for (int j = 0; j < 64; j++) {
            float pv[4], vv[4];
            #pragma unroll
            for (int r = 0; r < 4; r++) pv[r] = Ps[j * 65 + ty * 4 + r];
            #pragma unroll
            for (int c = 0; c < 4; c++) vv[c] = KVs[j * 65 + tx * 4 + c];
            #pragma unroll
            for (int r = 0; r < 4; r++)
                #pragma unroll
                for (int c = 0; c < 4; c++)
                    acc[r][c] += pv[r] * vv[c];
        }
    }

    // epilogue: divide by l, write h_attn[b, h*64+d, t]
    float* ob = g_att + ((size_t)bb * CC + (size_t)hh * HD) * TT;
    #pragma unroll
    for (int r = 0; r < 4; r++) {
        float linv = 1.f / lrow[ty * 4 + r];
        int i = i0 + ty * 4 + r;
        #pragma unroll
        for (int c = 0; c < 4; c++) {
            int d = tx * 4 + c;
            ob[(size_t)d * TT + i] = acc[r][c] * linv;
        }
    }
}

// ---------------------------------------------------------------------------
extern "C" void kernel_launch(void* const* d_in, const int* in_sizes, int n_in,
                              void* d_out, int out_size) {
    const float* x      = (const float*)d_in[0];
    const float* gamma  = (const float*)d_in[1];
    const float* beta   = (const float*)d_in[2];
    const float* qkv_w  = (const float*)d_in[3];
    const float* qkv_b  = (const float*)d_in[4];
    const float* proj_w = (const float*)d_in[5];
    const float* proj_b = (const float*)d_in[6];
    float* out = (float*)d_out;

    float *xn, *qkv, *att;
    cudaGetSymbolAddress((void**)&xn,  g_xn);
    cudaGetSymbolAddress((void**)&qkv, g_qkv);
    cudaGetSymbolAddress((void**)&att, g_att);

    // 1. GroupNorm
    gn_kernel<<<BB * NG, 256>>>(x, gamma, beta);

    // 2. QKV GEMM: [1536,512] x [512,1024] per batch, + bias
    dim3 g1(TT / 64, (3 * CC) / 64, BB);
    gemm_bias_kernel<<<g1, 256>>>(qkv_w, xn, qkv_b, nullptr, qkv, 3 * CC, CC);

    // 3. Flash attention
    cudaFuncSetAttribute(attn_kernel,
                         cudaFuncAttributeMaxDynamicSharedMemorySize,
                         ATTN_SMEM_BYTES);
    attn_kernel<<<dim3(TT / 64, NH, BB), 256, ATTN_SMEM_BYTES>>>();

    // 4. Proj GEMM + bias + residual -> d_out
    dim3 g2(TT / 64, CC / 64, BB);
    gemm_bias_kernel<<<g2, 256>>>(proj_w, att, proj_b, x, out, CC, CC);
}

// round 6
// speedup vs baseline: 1.4836x; 1.4836x over previous
#include <cuda_runtime.h>
#include <math.h>
#include <stdint.h>

#define BB 16
#define CC 512
#define TT 1024
#define NH 8
#define HD 64
#define NG 32
#define CPG 16

// Scratch (__device__ globals per allocation rules)
__device__ float g_xnt[BB * TT * CC];          // xn, t-major  [b][t][c]
__device__ float g_qkv[BB * 3 * CC * TT];      // [b][o][t]
__device__ float g_att[BB * TT * CC];          // h_attn, t-major [b][t][c]

__device__ __forceinline__ float f2tf32(float x) {
    float r;
    asm("cvt.rna.tf32.f32 %0, %1;" : "=f"(r) : "f"(x));
    return r;
}

__device__ __forceinline__ void mma_tf32_16x8x8(float* c, const uint32_t* a,
                                                uint32_t b0, uint32_t b1) {
    asm volatile(
        "mma.sync.aligned.m16n8k8.row.col.f32.tf32.tf32.f32 "
        "{%0,%1,%2,%3}, {%4,%5,%6,%7}, {%8,%9}, {%0,%1,%2,%3};"
        : "+f"(c[0]), "+f"(c[1]), "+f"(c[2]), "+f"(c[3])
        : "r"(a[0]), "r"(a[1]), "r"(a[2]), "r"(a[3]), "r"(b0), "r"(b1));
}

// ===========================================================================
// GroupNorm -> transposed output g_xnt[b][t][c]
// ===========================================================================
__global__ void gn_kernel(const float* __restrict__ x,
                          const float* __restrict__ gamma,
                          const float* __restrict__ beta) {
    int b = blockIdx.x >> 5;
    int g = blockIdx.x & 31;
    const float* xb = x + ((size_t)b * CC + (size_t)g * CPG) * TT;
    int tid = threadIdx.x;

    float s = 0.f, ss = 0.f;
    for (int i = tid; i < CPG * TT; i += 256) {
        float v = xb[i];
        s += v; ss += v * v;
    }
    __shared__ float rs[8], rss[8];
    #pragma unroll
    for (int o = 16; o > 0; o >>= 1) {
        s  += __shfl_down_sync(0xffffffff, s, o);
        ss += __shfl_down_sync(0xffffffff, ss, o);
    }
    if ((tid & 31) == 0) { rs[tid >> 5] = s; rss[tid >> 5] = ss; }
    __syncthreads();
    __shared__ float s_mean, s_inv;
    if (tid == 0) {
        float S = 0.f, SS = 0.f;
        #pragma unroll
        for (int i = 0; i < 8; i++) { S += rs[i]; SS += rss[i]; }
        float mean = S * (1.f / (CPG * TT));
        float var = SS * (1.f / (CPG * TT)) - mean * mean;
        s_mean = mean; s_inv = rsqrtf(var + 1e-5f);
    }
    __syncthreads();
    float mean = s_mean, inv = s_inv;

    __shared__ float gw[CPG], gb2[CPG];
    if (tid < CPG) {
        gw[tid]  = gamma[g * CPG + tid] * inv;
        gb2[tid] = beta[g * CPG + tid];
    }
    __shared__ float tile[CPG][257];
    float* outb = g_xnt + (size_t)b * TT * CC;

    for (int chunk = 0; chunk < 4; chunk++) {
        int t0 = chunk * 256;
        __syncthreads();
        for (int i = tid; i < CPG * 256; i += 256) {
            int c = i >> 8, t = i & 255;
            tile[c][t] = (xb[(size_t)c * TT + t0 + t] - mean) * gw[c] + gb2[c];
        }
        __syncthreads();
        for (int i = tid; i < 256 * CPG; i += 256) {
            int t = i >> 4, c = i & 15;
            outb[(size_t)(t0 + t) * CC + g * CPG + c] = tile[c][t];
        }
    }
}

// ===========================================================================
// tf32 mma.sync GEMM: D[t][o] = A[t][K] * W[o][K]^T  (+bias, +resid)
// CTA 128(t) x 128(o), 256 threads = 8 warps, warp tile 32(t) x 64(o).
// smem pitch 36 -> conflict-free LDS.32 fragment loads.
// Output written as Cm[b][o][t].
// ===========================================================================
#define GP 36

__global__ __launch_bounds__(256) void mma_gemm(
        const float* __restrict__ Am,    // [b][T][K] t-major
        const float* __restrict__ W,     // [Mout][K]
        const float* __restrict__ bias,  // [Mout]
        const float* __restrict__ resid, // [b][Mout][T] or null
        float* __restrict__ Cm,          // [b][Mout][T]
        int Mout) {
    __shared__ float As[128][GP];   // [t][k]
    __shared__ float Bs[128][GP];   // [o][k]

    int tid = threadIdx.x;
    int wid = tid >> 5, lane = tid & 31;
    int qm = lane >> 2, qk = lane & 3;
    int wm = wid & 3;          // t-warp: 0..3 -> rows wm*32
    int wn = wid >> 2;         // o-warp: 0..1 -> cols wn*64

    int t0 = blockIdx.x * 128, o0 = blockIdx.y * 128, b = blockIdx.z;
    const float* Ab = Am + ((size_t)b * TT + t0) * CC;
    const float* Wb = W + (size_t)o0 * CC;

    float acc[2][8][4];
    #pragma unroll
    for (int mt = 0; mt < 2; mt++)
        #pragma unroll
        for (int nt = 0; nt < 8; nt++)
            #pragma unroll
            for (int r = 0; r < 4; r++) acc[mt][nt][r] = 0.f;

    for (int kc = 0; kc < CC / 32; kc++) {
        int k0 = kc * 32;
        __syncthreads();
        #pragma unroll
        for (int q = 0; q < 4; q++) {
            int f = q * 256 + tid;
            int row = f >> 3, c4 = (f & 7) * 4;
            float4 av = *(const float4*)&Ab[(size_t)row * CC + k0 + c4];
            As[row][c4 + 0] = f2tf32(av.x);
            As[row][c4 + 1] = f2tf32(av.y);
            As[row][c4 + 2] = f2tf32(av.z);
            As[row][c4 + 3] = f2tf32(av.w);
            float4 bv = *(const float4*)&Wb[(size_t)row * CC + k0 + c4];
            Bs[row][c4 + 0] = f2tf32(bv.x);
            Bs[row][c4 + 1] = f2tf32(bv.y);
            Bs[row][c4 + 2] = f2tf32(bv.z);
            Bs[row][c4 + 3] = f2tf32(bv.w);
        }
        __syncthreads();

        #pragma unroll
        for (int ks = 0; ks < 4; ks++) {
            int kb = ks * 8;
            uint32_t af[2][4];
            #pragma unroll
            for (int mt = 0; mt < 2; mt++) {
                int r = wm * 32 + mt * 16 + qm;
                af[mt][0] = __float_as_uint(As[r][kb + qk]);
                af[mt][1] = __float_as_uint(As[r + 8][kb + qk]);
                af[mt][2] = __float_as_uint(As[r][kb + qk + 4]);
                af[mt][3] = __float_as_uint(As[r + 8][kb + qk + 4]);
            }
            #pragma unroll
            for (int nt = 0; nt < 8; nt++) {
                int cr = wn * 64 + nt * 8 + qm;       // o row in Bs, n = col of B
                uint32_t b0 = __float_as_uint(Bs[cr][kb + qk]);
                uint32_t b1 = __float_as_uint(Bs[cr][kb + qk + 4]);
                #pragma unroll
                for (int mt = 0; mt < 2; mt++)
                    mma_tf32_16x8x8(acc[mt][nt], af[mt], b0, b1);
            }
        }
    }

    // Epilogue: c0 -> (row=qm, col=2qk), c1 -> col+1, c2 -> row+8, c3 -> row+8,col+1
    #pragma unroll
    for (int mt = 0; mt < 2; mt++) {
        int tbase = t0 + wm * 32 + mt * 16 + qm;
        #pragma unroll
        for (int nt = 0; nt < 8; nt++) {
            int obase = o0 + wn * 64 + nt * 8 + 2 * qk;
            #pragma unroll
            for (int rr = 0; rr < 4; rr++) {
                int o = obase + (rr & 1);
                int t = tbase + (rr >> 1) * 8;
                size_t idx = ((size_t)b * Mout + o) * TT + t;
                float v = acc[mt][nt][rr] + bias[o];
                if (resid) v += resid[idx];
                Cm[idx] = v;
            }
        }
    }
}

// ===========================================================================
// Flash attention (SIMT) — writes t-major g_att[b][t][c]
// ===========================================================================
#define ATTN_SMEM_FLOATS (4096 + 4160 + 4160 + 192)
#define ATTN_SMEM_BYTES (ATTN_SMEM_FLOATS * 4)

__global__ void attn_kernel() {
    extern __shared__ float sm[];
    float* Qs  = sm;
    float* KVs = sm + 4096;
    float* Ps  = KVs + 4160;
    float* mrow = Ps + 4160;
    float* lrow = mrow + 64;
    float* rsc  = lrow + 64;

    int qt = blockIdx.x, hh = blockIdx.y, bb = blockIdx.z;
    int i0 = qt * 64;
    const float* qb = g_qkv + ((size_t)bb * 3 * CC + (size_t)hh * HD) * TT;
    const float* kb = qb + (size_t)CC * TT;
    const float* vb = kb + (size_t)CC * TT;

    int tid = threadIdx.x;
    int tx = tid & 15, ty = tid >> 4;

    for (int l = tid; l < 4096; l += 256) {
        int d = l >> 6, i = l & 63;
        Qs[d * 64 + i] = qb[(size_t)d * TT + i0 + i];
    }
    if (tid < 64) { mrow[tid] = -INFINITY; lrow[tid] = 0.f; }

    float acc[4][4] = {};
    const float scale = 0.125f;

    for (int kt = 0; kt < 16; kt++) {
        int j0 = kt * 64;
        __syncthreads();
        for (int l = tid; l < 4096; l += 256) {
            int d = l >> 6, j = l & 63;
            KVs[d * 65 + j] = kb[(size_t)d * TT + j0 + j];
        }
        __syncthreads();

        float s[4][4] = {};
        #pragma unroll
        for (int d = 0; d < 64; d++) {
            float qv[4], kv[4];
            #pragma unroll
            for (int r = 0; r < 4; r++) qv[r] = Qs[d * 64 + ty * 4 + r];
            #pragma unroll
            for (int c = 0; c < 4; c++) kv[c] = KVs[d * 65 + tx * 4 + c];
            #pragma unroll
            for (int r = 0; r < 4; r++)
                #pragma unroll
                for (int c = 0; c < 4; c++)
                    s[r][c] += qv[r] * kv[c];
        }
        #pragma unroll
        for (int r = 0; r < 4; r++)
            #pragma unroll
            for (int c = 0; c < 4; c++)
                Ps[(tx * 4 + c) * 65 + ty * 4 + r] = s[r][c] * scale;
        __syncthreads();

        if (tid < 64) {
            int i = tid;
            float m = mrow[i];
            float nm = m;
            #pragma unroll 8
            for (int j = 0; j < 64; j++) nm = fmaxf(nm, Ps[j * 65 + i]);
            float rs_ = __expf(m - nm);
            float li = lrow[i] * rs_;
            #pragma unroll 8
            for (int j = 0; j < 64; j++) {
                float p = __expf(Ps[j * 65 + i] - nm);
                Ps[j * 65 + i] = p;
                li += p;
            }
            mrow[i] = nm;
            lrow[i] = li;
            rsc[i] = rs_;
        } else {
            int t2 = tid - 64;
            for (int l = t2; l < 4096; l += 192) {
                int d = l >> 6, j = l & 63;
                KVs[j * 65 + d] = vb[(size_t)d * TT + j0 + j];
            }
        }
        __syncthreads();

        #pragma unroll
        for (int r = 0; r < 4; r++) {
            float sc = rsc[ty * 4 + r];
            #pragma unroll
            for (int c = 0; c < 4; c++) acc[r][c] *= sc;
        }
        #pragma unroll
        for (int j = 0; j < 64; j++) {
            float pv[4], vv[4];
            #pragma unroll
            for (int r = 0; r < 4; r++) pv[r] = Ps[j * 65 + ty * 4 + r];
            #pragma unroll
            for (int c = 0; c < 4; c++) vv[c] = KVs[j * 65 + tx * 4 + c];
            #pragma unroll
            for (int r = 0; r < 4; r++)
                #pragma unroll
                for (int c = 0; c < 4; c++)
                    acc[r][c] += pv[r] * vv[c];
        }
    }

    // epilogue: write t-major h_attn[b][t][c], float4 along c
    float* ob = g_att + (size_t)bb * TT * CC;
    #pragma unroll
    for (int r = 0; r < 4; r++) {
        float linv = 1.f / lrow[ty * 4 + r];
        size_t rowoff = (size_t)(i0 + ty * 4 + r) * CC + hh * HD + tx * 4;
        float4 v = make_float4(acc[r][0] * linv, acc[r][1] * linv,
                               acc[r][2] * linv, acc[r][3] * linv);
        *(float4*)&ob[rowoff] = v;
    }
}

// ===========================================================================
extern "C" void kernel_launch(void* const* d_in, const int* in_sizes, int n_in,
                              void* d_out, int out_size) {
    const float* x      = (const float*)d_in[0];
    const float* gamma  = (const float*)d_in[1];
    const float* beta   = (const float*)d_in[2];
    const float* qkv_w  = (const float*)d_in[3];
    const float* qkv_b  = (const float*)d_in[4];
    const float* proj_w = (const float*)d_in[5];
    const float* proj_b = (const float*)d_in[6];
    float* out = (float*)d_out;

    float *xnt, *qkv, *att;
    cudaGetSymbolAddress((void**)&xnt, g_xnt);
    cudaGetSymbolAddress((void**)&qkv, g_qkv);
    cudaGetSymbolAddress((void**)&att, g_att);

    static int inited = 0;
    if (!inited) {
        cudaFuncSetAttribute(attn_kernel,
                             cudaFuncAttributeMaxDynamicSharedMemorySize,
                             ATTN_SMEM_BYTES);
        inited = 1;
    }

    // 1. GroupNorm -> xn_t [b][t][c]
    gn_kernel<<<BB * NG, 256>>>(x, gamma, beta);

    // 2. QKV GEMM (tf32 mma.sync): out [b][1536][t]
    mma_gemm<<<dim3(TT / 128, (3 * CC) / 128, BB), 256>>>(
        xnt, qkv_w, qkv_b, nullptr, qkv, 3 * CC);

    // 3. Flash attention -> g_att [b][t][c]
    attn_kernel<<<dim3(TT / 64, NH, BB), 256, ATTN_SMEM_BYTES>>>();

    // 4. Proj GEMM (tf32 mma.sync) + bias + residual -> d_out [b][c][t]
    mma_gemm<<<dim3(TT / 128, CC / 128, BB), 256>>>(
        att, proj_w, proj_b, x, out, CC);
}

// round 7
// speedup vs baseline: 3.1071x; 2.0943x over previous
#include <cuda_runtime.h>
#include <math.h>
#include <stdint.h>

#define BB 16
#define CC 512
#define TT 1024
#define NH 8
#define HD 64
#define NG 32
#define CPG 16

// Scratch (__device__ globals per allocation rules)
__device__ float g_xnt[BB * TT * CC];          // xn, t-major  [b][t][c]
__device__ float g_qkv[BB * 3 * CC * TT];      // [b][o][t]
__device__ float g_att[BB * TT * CC];          // h_attn, t-major [b][t][c]

__device__ __forceinline__ float f2tf32(float x) {
    float r;
    asm("cvt.rna.tf32.f32 %0, %1;" : "=f"(r) : "f"(x));
    return r;
}

__device__ __forceinline__ void mma_tf32_16x8x8(float* c, const uint32_t* a,
                                                uint32_t b0, uint32_t b1) {
    asm volatile(
        "mma.sync.aligned.m16n8k8.row.col.f32.tf32.tf32.f32 "
        "{%0,%1,%2,%3}, {%4,%5,%6,%7}, {%8,%9}, {%0,%1,%2,%3};"
        : "+f"(c[0]), "+f"(c[1]), "+f"(c[2]), "+f"(c[3])
        : "r"(a[0]), "r"(a[1]), "r"(a[2]), "r"(a[3]), "r"(b0), "r"(b1));
}

// ===========================================================================
// GroupNorm -> transposed output g_xnt[b][t][c]
// ===========================================================================
__global__ void gn_kernel(const float* __restrict__ x,
                          const float* __restrict__ gamma,
                          const float* __restrict__ beta) {
    int b = blockIdx.x >> 5;
    int g = blockIdx.x & 31;
    const float* xb = x + ((size_t)b * CC + (size_t)g * CPG) * TT;
    int tid = threadIdx.x;

    float s = 0.f, ss = 0.f;
    for (int i = tid; i < CPG * TT; i += 256) {
        float v = xb[i];
        s += v; ss += v * v;
    }
    __shared__ float rs[8], rss[8];
    #pragma unroll
    for (int o = 16; o > 0; o >>= 1) {
        s  += __shfl_down_sync(0xffffffff, s, o);
        ss += __shfl_down_sync(0xffffffff, ss, o);
    }
    if ((tid & 31) == 0) { rs[tid >> 5] = s; rss[tid >> 5] = ss; }
    __syncthreads();
    __shared__ float s_mean, s_inv;
    if (tid == 0) {
        float S = 0.f, SS = 0.f;
        #pragma unroll
        for (int i = 0; i < 8; i++) { S += rs[i]; SS += rss[i]; }
        float mean = S * (1.f / (CPG * TT));
        float var = SS * (1.f / (CPG * TT)) - mean * mean;
        s_mean = mean; s_inv = rsqrtf(var + 1e-5f);
    }
    __syncthreads();
    float mean = s_mean, inv = s_inv;

    __shared__ float gw[CPG], gb2[CPG];
    if (tid < CPG) {
        gw[tid]  = gamma[g * CPG + tid] * inv;
        gb2[tid] = beta[g * CPG + tid];
    }
    __shared__ float tile[CPG][257];
    float* outb = g_xnt + (size_t)b * TT * CC;

    for (int chunk = 0; chunk < 4; chunk++) {
        int t0 = chunk * 256;
        __syncthreads();
        for (int i = tid; i < CPG * 256; i += 256) {
            int c = i >> 8, t = i & 255;
            tile[c][t] = (xb[(size_t)c * TT + t0 + t] - mean) * gw[c] + gb2[c];
        }
        __syncthreads();
        for (int i = tid; i < 256 * CPG; i += 256) {
            int t = i >> 4, c = i & 15;
            outb[(size_t)(t0 + t) * CC + g * CPG + c] = tile[c][t];
        }
    }
}

// ===========================================================================
// tf32 mma.sync GEMM (verified round 6): D[t][o] = A[t][K]*W[o][K]^T
// ===========================================================================
#define GP 36

__global__ __launch_bounds__(256) void mma_gemm(
        const float* __restrict__ Am,    // [b][T][K] t-major
        const float* __restrict__ W,     // [Mout][K]
        const float* __restrict__ bias,  // [Mout]
        const float* __restrict__ resid, // [b][Mout][T] or null
        float* __restrict__ Cm,          // [b][Mout][T]
        int Mout) {
    __shared__ float As[128][GP];   // [t][k]
    __shared__ float Bs[128][GP];   // [o][k]

    int tid = threadIdx.x;
    int wid = tid >> 5, lane = tid & 31;
    int qm = lane >> 2, qk = lane & 3;
    int wm = wid & 3;
    int wn = wid >> 2;

    int t0 = blockIdx.x * 128, o0 = blockIdx.y * 128, b = blockIdx.z;
    const float* Ab = Am + ((size_t)b * TT + t0) * CC;
    const float* Wb = W + (size_t)o0 * CC;

    float acc[2][8][4];
    #pragma unroll
    for (int mt = 0; mt < 2; mt++)
        #pragma unroll
        for (int nt = 0; nt < 8; nt++)
            #pragma unroll
            for (int r = 0; r < 4; r++) acc[mt][nt][r] = 0.f;

    for (int kc = 0; kc < CC / 32; kc++) {
        int k0 = kc * 32;
        __syncthreads();
        #pragma unroll
        for (int q = 0; q < 4; q++) {
            int f = q * 256 + tid;
            int row = f >> 3, c4 = (f & 7) * 4;
            float4 av = *(const float4*)&Ab[(size_t)row * CC + k0 + c4];
            As[row][c4 + 0] = f2tf32(av.x);
            As[row][c4 + 1] = f2tf32(av.y);
            As[row][c4 + 2] = f2tf32(av.z);
            As[row][c4 + 3] = f2tf32(av.w);
            float4 bv = *(const float4*)&Wb[(size_t)row * CC + k0 + c4];
            Bs[row][c4 + 0] = f2tf32(bv.x);
            Bs[row][c4 + 1] = f2tf32(bv.y);
            Bs[row][c4 + 2] = f2tf32(bv.z);
            Bs[row][c4 + 3] = f2tf32(bv.w);
        }
        __syncthreads();

        #pragma unroll
        for (int ks = 0; ks < 4; ks++) {
            int kb = ks * 8;
            uint32_t af[2][4];
            #pragma unroll
            for (int mt = 0; mt < 2; mt++) {
                int r = wm * 32 + mt * 16 + qm;
                af[mt][0] = __float_as_uint(As[r][kb + qk]);
                af[mt][1] = __float_as_uint(As[r + 8][kb + qk]);
                af[mt][2] = __float_as_uint(As[r][kb + qk + 4]);
                af[mt][3] = __float_as_uint(As[r + 8][kb + qk + 4]);
            }
            #pragma unroll
            for (int nt = 0; nt < 8; nt++) {
                int cr = wn * 64 + nt * 8 + qm;
                uint32_t b0 = __float_as_uint(Bs[cr][kb + qk]);
                uint32_t b1 = __float_as_uint(Bs[cr][kb + qk + 4]);
                #pragma unroll
                for (int mt = 0; mt < 2; mt++)
                    mma_tf32_16x8x8(acc[mt][nt], af[mt], b0, b1);
            }
        }
    }

    #pragma unroll
    for (int mt = 0; mt < 2; mt++) {
        int tbase = t0 + wm * 32 + mt * 16 + qm;
        #pragma unroll
        for (int nt = 0; nt < 8; nt++) {
            int obase = o0 + wn * 64 + nt * 8 + 2 * qk;
            #pragma unroll
            for (int rr = 0; rr < 4; rr++) {
                int o = obase + (rr & 1);
                int t = tbase + (rr >> 1) * 8;
                size_t idx = ((size_t)b * Mout + o) * TT + t;
                float v = acc[mt][nt][rr] + bias[o];
                if (resid) v += resid[idx];
                Cm[idx] = v;
            }
        }
    }
}

// ===========================================================================
// tf32 mma.sync flash attention.
// Block: 128 queries x (b,h). 8 warps, warp = 16 query rows.
// K/V streamed in 64-key tiles, natural [d][t] smem layout (no transpose).
// Online softmax in registers (shfl over the 4 lanes sharing a row).
// ===========================================================================
#define QT 128
#define KT 64
#define KSP 72
#define VSP 68
#define PSP 68
#define ATT_SMEM ((64 * KSP + 64 * VSP + 128 * PSP) * 4)

__global__ __launch_bounds__(256) void mma_attn() {
    extern __shared__ float sm[];
    float* Ks = sm;                         // [d][j] pitch KSP
    float* Vs = sm + 64 * KSP;              // [d][j] pitch VSP
    float* Ps = sm + 64 * KSP + 64 * VSP;   // [i][j] pitch PSP

    int qt = blockIdx.x, hh = blockIdx.y, bb = blockIdx.z;
    int i0 = qt * QT;
    const float* qb = g_qkv + ((size_t)bb * 3 * CC + (size_t)hh * HD) * TT;
    const float* kb = qb + (size_t)CC * TT;
    const float* vb = kb + (size_t)CC * TT;

    int tid = threadIdx.x, wid = tid >> 5, lane = tid & 31;
    int qm = lane >> 2, qk = lane & 3;
    int wr = wid * 16;

    // Q fragments in registers, pre-scaled by 1/sqrt(64), tf32
    uint32_t qf[8][4];
    {
        int r1 = i0 + wr + qm;
        #pragma unroll
        for (int ks = 0; ks < 8; ks++) {
            int d0 = ks * 8 + qk;
            qf[ks][0] = __float_as_uint(f2tf32(0.125f * qb[(size_t)d0 * TT + r1]));
            qf[ks][1] = __float_as_uint(f2tf32(0.125f * qb[(size_t)d0 * TT + r1 + 8]));
            qf[ks][2] = __float_as_uint(f2tf32(0.125f * qb[(size_t)(d0 + 4) * TT + r1]));
            qf[ks][3] = __float_as_uint(f2tf32(0.125f * qb[(size_t)(d0 + 4) * TT + r1 + 8]));
        }
    }

    float oacc[8][4];
    #pragma unroll
    for (int nt = 0; nt < 8; nt++)
        #pragma unroll
        for (int r = 0; r < 4; r++) oacc[nt][r] = 0.f;
    float m1 = -INFINITY, m2 = -INFINITY, l1 = 0.f, l2 = 0.f;

    for (int kt = 0; kt < 16; kt++) {
        int j0 = kt * KT;
        __syncthreads();   // all warps done with prev Ks/Vs
        #pragma unroll
        for (int q = 0; q < 4; q++) {
            int f = q * 256 + tid;
            int d = f >> 4, j4 = (f & 15) * 4;
            float4 kv = *(const float4*)&kb[(size_t)d * TT + j0 + j4];
            Ks[d * KSP + j4 + 0] = f2tf32(kv.x);
            Ks[d * KSP + j4 + 1] = f2tf32(kv.y);
            Ks[d * KSP + j4 + 2] = f2tf32(kv.z);
            Ks[d * KSP + j4 + 3] = f2tf32(kv.w);
            float4 vv = *(const float4*)&vb[(size_t)d * TT + j0 + j4];
            Vs[d * VSP + j4 + 0] = f2tf32(vv.x);
            Vs[d * VSP + j4 + 1] = f2tf32(vv.y);
            Vs[d * VSP + j4 + 2] = f2tf32(vv.z);
            Vs[d * VSP + j4 + 3] = f2tf32(vv.w);
        }
        __syncthreads();

        // S = Q K^T  (B-frag from Ks[k=d][n=j], conflict-free pitch 72)
        float sacc[8][4];
        #pragma unroll
        for (int nt = 0; nt < 8; nt++)
            #pragma unroll
            for (int r = 0; r < 4; r++) sacc[nt][r] = 0.f;
        #pragma unroll
        for (int ks = 0; ks < 8; ks++) {
            #pragma unroll
            for (int nt = 0; nt < 8; nt++) {
                uint32_t b0 = __float_as_uint(Ks[(ks * 8 + qk) * KSP + nt * 8 + qm]);
                uint32_t b1 = __float_as_uint(Ks[(ks * 8 + qk + 4) * KSP + nt * 8 + qm]);
                mma_tf32_16x8x8(sacc[nt], qf[ks], b0, b1);
            }
        }

        // online softmax in registers; rows r1=wr+qm (c0,c1), r2=wr+qm+8 (c2,c3)
        float tm1 = -INFINITY, tm2 = -INFINITY;
        #pragma unroll
        for (int nt = 0; nt < 8; nt++) {
            tm1 = fmaxf(tm1, fmaxf(sacc[nt][0], sacc[nt][1]));
            tm2 = fmaxf(tm2, fmaxf(sacc[nt][2], sacc[nt][3]));
        }
        tm1 = fmaxf(tm1, __shfl_xor_sync(0xffffffff, tm1, 1));
        tm1 = fmaxf(tm1, __shfl_xor_sync(0xffffffff, tm1, 2));
        tm2 = fmaxf(tm2, __shfl_xor_sync(0xffffffff, tm2, 1));
        tm2 = fmaxf(tm2, __shfl_xor_sync(0xffffffff, tm2, 2));
        float nm1 = fmaxf(m1, tm1), nm2 = fmaxf(m2, tm2);
        float sc1 = __expf(m1 - nm1), sc2 = __expf(m2 - nm2);

        float rs1 = 0.f, rs2 = 0.f;
        #pragma unroll
        for (int nt = 0; nt < 8; nt++) {
            float p0 = __expf(sacc[nt][0] - nm1);
            float p1 = __expf(sacc[nt][1] - nm1);
            float p2 = __expf(sacc[nt][2] - nm2);
            float p3 = __expf(sacc[nt][3] - nm2);
            rs1 += p0 + p1;
            rs2 += p2 + p3;
            *(float2*)&Ps[(wr + qm) * PSP + nt * 8 + 2 * qk] =
                make_float2(f2tf32(p0), f2tf32(p1));
            *(float2*)&Ps[(wr + qm + 8) * PSP + nt * 8 + 2 * qk] =
                make_float2(f2tf32(p2), f2tf32(p3));
        }
        rs1 += __shfl_xor_sync(0xffffffff, rs1, 1);
        rs1 += __shfl_xor_sync(0xffffffff, rs1, 2);
        rs2 += __shfl_xor_sync(0xffffffff, rs2, 1);
        rs2 += __shfl_xor_sync(0xffffffff, rs2, 2);
        l1 = l1 * sc1 + rs1;
        l2 = l2 * sc2 + rs2;
        m1 = nm1; m2 = nm2;

        #pragma unroll
        for (int nt = 0; nt < 8; nt++) {
            oacc[nt][0] *= sc1; oacc[nt][1] *= sc1;
            oacc[nt][2] *= sc2; oacc[nt][3] *= sc2;
        }
        __syncwarp();   // Ps rows are warp-private: warp-level ordering suffices

        // O += P V   (A-frag from Ps, B-frag from Vs[n=d][k=j])
        #pragma unroll
        for (int ks = 0; ks < 8; ks++) {
            uint32_t af[4];
            af[0] = __float_as_uint(Ps[(wr + qm) * PSP + ks * 8 + qk]);
            af[1] = __float_as_uint(Ps[(wr + qm + 8) * PSP + ks * 8 + qk]);
            af[2] = __float_as_uint(Ps[(wr + qm) * PSP + ks * 8 + qk + 4]);
            af[3] = __float_as_uint(Ps[(wr + qm + 8) * PSP + ks * 8 + qk + 4]);
            #pragma unroll
            for (int nt = 0; nt < 8; nt++) {
                uint32_t b0 = __float_as_uint(Vs[(nt * 8 + qm) * VSP + ks * 8 + qk]);
                uint32_t b1 = __float_as_uint(Vs[(nt * 8 + qm) * VSP + ks * 8 + qk + 4]);
                mma_tf32_16x8x8(oacc[nt], af, b0, b1);
            }
        }
    }

    // epilogue: O/l -> g_att[b][t][c]
    float li1 = 1.f / l1, li2 = 1.f / l2;
    float* ob = g_att + (size_t)bb * TT * CC;
    int r1 = i0 + wr + qm, r2 = r1 + 8;
    int cb = hh * HD;
    #pragma unroll
    for (int nt = 0; nt < 8; nt++) {
        *(float2*)&ob[(size_t)r1 * CC + cb + nt * 8 + 2 * qk] =
            make_float2(oacc[nt][0] * li1, oacc[nt][1] * li1);
        *(float2*)&ob[(size_t)r2 * CC + cb + nt * 8 + 2 * qk] =
            make_float2(oacc[nt][2] * li2, oacc[nt][3] * li2);
    }
}

// ===========================================================================
extern "C" void kernel_launch(void* const* d_in, const int* in_sizes, int n_in,
                              void* d_out, int out_size) {
    const float* x      = (const float*)d_in[0];
    const float* gamma  = (const float*)d_in[1];
    const float* beta   = (const float*)d_in[2];
    const float* qkv_w  = (const float*)d_in[3];
    const float* qkv_b  = (const float*)d_in[4];
    const float* proj_w = (const float*)d_in[5];
    const float* proj_b = (const float*)d_in[6];
    float* out = (float*)d_out;

    float *xnt, *qkv, *att;
    cudaGetSymbolAddress((void**)&xnt, g_xnt);
    cudaGetSymbolAddress((void**)&qkv, g_qkv);
    cudaGetSymbolAddress((void**)&att, g_att);

    static int inited = 0;
    if (!inited) {
        cudaFuncSetAttribute(mma_attn,
                             cudaFuncAttributeMaxDynamicSharedMemorySize,
                             ATT_SMEM);
        inited = 1;
    }

    // 1. GroupNorm -> xn_t [b][t][c]
    gn_kernel<<<BB * NG, 256>>>(x, gamma, beta);

    // 2. QKV GEMM (tf32 mma.sync): out [b][1536][t]
    mma_gemm<<<dim3(TT / 128, (3 * CC) / 128, BB), 256>>>(
        xnt, qkv_w, qkv_b, nullptr, qkv, 3 * CC);

    // 3. Flash attention (tf32 mma.sync) -> g_att [b][t][c]
    mma_attn<<<dim3(TT / QT, NH, BB), 256, ATT_SMEM>>>();

    // 4. Proj GEMM (tf32 mma.sync) + bias + residual -> d_out [b][c][t]
    mma_gemm<<<dim3(TT / 128, CC / 128, BB), 256>>>(
        att, proj_w, proj_b, x, out, CC);
}

// round 8
// speedup vs baseline: 4.2406x; 1.3648x over previous
#include <cuda_runtime.h>
#include <math.h>
#include <stdint.h>

#define BB 16
#define CC 512
#define TT 1024
#define NH 8
#define HD 64
#define NG 32
#define CPG 16

// Scratch (__device__ globals per allocation rules)
__device__ float g_xnt[BB * TT * CC];          // xn, t-major  [b][t][c]
__device__ float g_qkv[BB * 3 * CC * TT];      // [b][o][t]
__device__ float g_att[BB * TT * CC];          // h_attn, t-major [b][t][c]

__device__ __forceinline__ float f2tf32(float x) {
    float r;
    asm("cvt.rna.tf32.f32 %0, %1;" : "=f"(r) : "f"(x));
    return r;
}

__device__ __forceinline__ uint32_t smem_u32(const void* p) {
    uint32_t a;
    asm("{ .reg .u64 t; cvta.to.shared.u64 t, %1; cvt.u32.u64 %0, t; }"
        : "=r"(a) : "l"(p));
    return a;
}

__device__ __forceinline__ void cp16(uint32_t sdst, const void* gsrc) {
    asm volatile("cp.async.ca.shared.global [%0], [%1], 16;"
                 :: "r"(sdst), "l"(gsrc));
}
#define CP_COMMIT() asm volatile("cp.async.commit_group;" ::: "memory")
#define CP_WAIT0()  asm volatile("cp.async.wait_group 0;" ::: "memory")

__device__ __forceinline__ void mma_tf32_16x8x8(float* c, const uint32_t* a,
                                                uint32_t b0, uint32_t b1) {
    asm volatile(
        "mma.sync.aligned.m16n8k8.row.col.f32.tf32.tf32.f32 "
        "{%0,%1,%2,%3}, {%4,%5,%6,%7}, {%8,%9}, {%0,%1,%2,%3};"
        : "+f"(c[0]), "+f"(c[1]), "+f"(c[2]), "+f"(c[3])
        : "r"(a[0]), "r"(a[1]), "r"(a[2]), "r"(a[3]), "r"(b0), "r"(b1));
}

// ===========================================================================
// GroupNorm -> transposed output g_xnt[b][t][c]
// ===========================================================================
__global__ void gn_kernel(const float* __restrict__ x,
                          const float* __restrict__ gamma,
                          const float* __restrict__ beta) {
    int b = blockIdx.x >> 5;
    int g = blockIdx.x & 31;
    const float* xb = x + ((size_t)b * CC + (size_t)g * CPG) * TT;
    int tid = threadIdx.x;

    float s = 0.f, ss = 0.f;
    for (int i = tid; i < CPG * TT; i += 256) {
        float v = xb[i];
        s += v; ss += v * v;
    }
    __shared__ float rs[8], rss[8];
    #pragma unroll
    for (int o = 16; o > 0; o >>= 1) {
        s  += __shfl_down_sync(0xffffffff, s, o);
        ss += __shfl_down_sync(0xffffffff, ss, o);
    }
    if ((tid & 31) == 0) { rs[tid >> 5] = s; rss[tid >> 5] = ss; }
    __syncthreads();
    __shared__ float s_mean, s_inv;
    if (tid == 0) {
        float S = 0.f, SS = 0.f;
        #pragma unroll
        for (int i = 0; i < 8; i++) { S += rs[i]; SS += rss[i]; }
        float mean = S * (1.f / (CPG * TT));
        float var = SS * (1.f / (CPG * TT)) - mean * mean;
        s_mean = mean; s_inv = rsqrtf(var + 1e-5f);
    }
    __syncthreads();
    float mean = s_mean, inv = s_inv;

    __shared__ float gw[CPG], gb2[CPG];
    if (tid < CPG) {
        gw[tid]  = gamma[g * CPG + tid] * inv;
        gb2[tid] = beta[g * CPG + tid];
    }
    __shared__ float tile[CPG][257];
    float* outb = g_xnt + (size_t)b * TT * CC;

    for (int chunk = 0; chunk < 4; chunk++) {
        int t0 = chunk * 256;
        __syncthreads();
        for (int i = tid; i < CPG * 256; i += 256) {
            int c = i >> 8, t = i & 255;
            tile[c][t] = (xb[(size_t)c * TT + t0 + t] - mean) * gw[c] + gb2[c];
        }
        __syncthreads();
        for (int i = tid; i < 256 * CPG; i += 256) {
            int t = i >> 4, c = i & 15;
            outb[(size_t)(t0 + t) * CC + g * CPG + c] = tile[c][t];
        }
    }
}

// ===========================================================================
// tf32 mma.sync GEMM with cp.async double-buffering.
// D[t][o] = A[t][K]*W[o][K]^T ; CTA 128x128, warp 32x64. Raw fp32 in smem
// (tf32 MMA truncates low mantissa bits in hardware).
// ===========================================================================
#define GP 36
#define GEMM_SMEM (4 * 128 * GP * 4)   // As[2]+Bs[2]

__global__ __launch_bounds__(256) void mma_gemm(
        const float* __restrict__ Am,    // [b][T][K] t-major
        const float* __restrict__ W,     // [Mout][K]
        const float* __restrict__ bias,  // [Mout]
        const float* __restrict__ resid, // [b][Mout][T] or null
        float* __restrict__ Cm,          // [b][Mout][T]
        int Mout) {
    extern __shared__ float smg[];
    float* As = smg;                    // [2][128][GP]
    float* Bs = smg + 2 * 128 * GP;     // [2][128][GP]
    uint32_t sa = smem_u32(As), sb2 = smem_u32(Bs);

    int tid = threadIdx.x;
    int wid = tid >> 5, lane = tid & 31;
    int qm = lane >> 2, qk = lane & 3;
    int wm = wid & 3;
    int wn = wid >> 2;

    int t0 = blockIdx.x * 128, o0 = blockIdx.y * 128, b = blockIdx.z;
    const float* Ab = Am + ((size_t)b * TT + t0) * CC;
    const float* Wb = W + (size_t)o0 * CC;

    int lrow = tid >> 3, lc4 = (tid & 7) * 4;   // 128 rows x 8 chunks of 4

    float acc[2][8][4];
    #pragma unroll
    for (int mt = 0; mt < 2; mt++)
        #pragma unroll
        for (int nt = 0; nt < 8; nt++)
            #pragma unroll
            for (int r = 0; r < 4; r++) acc[mt][nt][r] = 0.f;

    #define G_LOAD(kt, buf) do {                                               \
        int _k0 = (kt) * 32;                                                   \
        uint32_t _ab = sa + (uint32_t)(buf) * 128 * GP * 4;                    \
        uint32_t _bb = sb2 + (uint32_t)(buf) * 128 * GP * 4;                   \
        _Pragma("unroll")                                                      \
        for (int q = 0; q < 4; q++) {                                          \
            int row = (q * 32) + lrow;                                         \
            cp16(_ab + (uint32_t)(row * GP + lc4) * 4,                         \
                 &Ab[(size_t)row * CC + _k0 + lc4]);                           \
            cp16(_bb + (uint32_t)(row * GP + lc4) * 4,                         \
                 &Wb[(size_t)row * CC + _k0 + lc4]);                           \
        }                                                                      \
    } while (0)

    G_LOAD(0, 0);
    CP_COMMIT();

    for (int kc = 0; kc < 16; kc++) {
        CP_WAIT0();
        __syncthreads();
        if (kc + 1 < 16) { G_LOAD(kc + 1, (kc + 1) & 1); CP_COMMIT(); }

        const float* Ac = As + (kc & 1) * 128 * GP;
        const float* Bc = Bs + (kc & 1) * 128 * GP;
        #pragma unroll
        for (int ks = 0; ks < 4; ks++) {
            int kb = ks * 8;
            uint32_t af[2][4];
            #pragma unroll
            for (int mt = 0; mt < 2; mt++) {
                int r = wm * 32 + mt * 16 + qm;
                af[mt][0] = __float_as_uint(Ac[r * GP + kb + qk]);
                af[mt][1] = __float_as_uint(Ac[(r + 8) * GP + kb + qk]);
                af[mt][2] = __float_as_uint(Ac[r * GP + kb + qk + 4]);
                af[mt][3] = __float_as_uint(Ac[(r + 8) * GP + kb + qk + 4]);
            }
            #pragma unroll
            for (int nt = 0; nt < 8; nt++) {
                int cr = wn * 64 + nt * 8 + qm;
                uint32_t b0 = __float_as_uint(Bc[cr * GP + kb + qk]);
                uint32_t b1 = __float_as_uint(Bc[cr * GP + kb + qk + 4]);
                #pragma unroll
                for (int mt = 0; mt < 2; mt++)
                    mma_tf32_16x8x8(acc[mt][nt], af[mt], b0, b1);
            }
        }
    }

    #pragma unroll
    for (int mt = 0; mt < 2; mt++) {
        int tbase = t0 + wm * 32 + mt * 16 + qm;
        #pragma unroll
        for (int nt = 0; nt < 8; nt++) {
            int obase = o0 + wn * 64 + nt * 8 + 2 * qk;
            #pragma unroll
            for (int rr = 0; rr < 4; rr++) {
                int o = obase + (rr & 1);
                int t = tbase + (rr >> 1) * 8;
                size_t idx = ((size_t)b * Mout + o) * TT + t;
                float v = acc[mt][nt][rr] + bias[o];
                if (resid) v += resid[idx];
                Cm[idx] = v;
            }
        }
    }
}

// ===========================================================================
// tf32 mma.sync flash attention with cp.async double-buffered K/V.
// Block: 128 queries x (b,h). 8 warps, warp = 16 query rows.
// ===========================================================================
#define QT 128
#define KT 64
#define KSP 72
#define VSP 68
#define PSP 68
#define KBUF (64 * KSP)
#define VBUF (64 * VSP)
#define ATT_SMEM ((2 * KBUF + 2 * VBUF + 128 * PSP) * 4)

__global__ __launch_bounds__(256) void mma_attn() {
    extern __shared__ float sm[];
    float* Ks = sm;                          // [2][64][KSP]
    float* Vs = sm + 2 * KBUF;               // [2][64][VSP]
    float* Ps = sm + 2 * KBUF + 2 * VBUF;    // [128][PSP]
    uint32_t ks_a = smem_u32(Ks), vs_a = smem_u32(Vs);

    int qt = blockIdx.x, hh = blockIdx.y, bb = blockIdx.z;
    int i0 = qt * QT;
    const float* qb = g_qkv + ((size_t)bb * 3 * CC + (size_t)hh * HD) * TT;
    const float* kb = qb + (size_t)CC * TT;
    const float* vb = kb + (size_t)CC * TT;

    int tid = threadIdx.x, wid = tid >> 5, lane = tid & 31;
    int qm = lane >> 2, qk = lane & 3;
    int wr = wid * 16;

    int ld = tid >> 4, lj4 = (tid & 15) * 4;  // 16 d-rows per pass x 16 j-chunks

    #define KV_LOAD(kt, buf) do {                                              \
        int _j0 = (kt) * KT;                                                   \
        uint32_t _ka = ks_a + (uint32_t)(buf) * KBUF * 4;                      \
        uint32_t _va = vs_a + (uint32_t)(buf) * VBUF * 4;                      \
        _Pragma("unroll")                                                      \
        for (int q = 0; q < 4; q++) {                                          \
            int d = q * 16 + ld;                                               \
            cp16(_ka + (uint32_t)(d * KSP + lj4) * 4,                          \
                 &kb[(size_t)d * TT + _j0 + lj4]);                             \
            cp16(_va + (uint32_t)(d * VSP + lj4) * 4,                          \
                 &vb[(size_t)d * TT + _j0 + lj4]);                             \
        }                                                                      \
    } while (0)

    KV_LOAD(0, 0);
    CP_COMMIT();

    // Q fragments in registers, pre-scaled by 1/sqrt(64), tf32(rna)
    uint32_t qf[8][4];
    {
        int r1 = i0 + wr + qm;
        #pragma unroll
        for (int ks = 0; ks < 8; ks++) {
            int d0 = ks * 8 + qk;
            qf[ks][0] = __float_as_uint(f2tf32(0.125f * qb[(size_t)d0 * TT + r1]));
            qf[ks][1] = __float_as_uint(f2tf32(0.125f * qb[(size_t)d0 * TT + r1 + 8]));
            qf[ks][2] = __float_as_uint(f2tf32(0.125f * qb[(size_t)(d0 + 4) * TT + r1]));
            qf[ks][3] = __float_as_uint(f2tf32(0.125f * qb[(size_t)(d0 + 4) * TT + r1 + 8]));
        }
    }

    float oacc[8][4];
    #pragma unroll
    for (int nt = 0; nt < 8; nt++)
        #pragma unroll
        for (int r = 0; r < 4; r++) oacc[nt][r] = 0.f;
    float m1 = -INFINITY, m2 = -INFINITY, l1 = 0.f, l2 = 0.f;

    for (int kt = 0; kt < 16; kt++) {
        CP_WAIT0();
        __syncthreads();
        if (kt + 1 < 16) { KV_LOAD(kt + 1, (kt + 1) & 1); CP_COMMIT(); }

        const float* Kc = Ks + (kt & 1) * KBUF;
        const float* Vc = Vs + (kt & 1) * VBUF;

        // S = Q K^T
        float sacc[8][4];
        #pragma unroll
        for (int nt = 0; nt < 8; nt++)
            #pragma unroll
            for (int r = 0; r < 4; r++) sacc[nt][r] = 0.f;
        #pragma unroll
        for (int ks = 0; ks < 8; ks++) {
            #pragma unroll
            for (int nt = 0; nt < 8; nt++) {
                uint32_t b0 = __float_as_uint(Kc[(ks * 8 + qk) * KSP + nt * 8 + qm]);
                uint32_t b1 = __float_as_uint(Kc[(ks * 8 + qk + 4) * KSP + nt * 8 + qm]);
                mma_tf32_16x8x8(sacc[nt], qf[ks], b0, b1);
            }
        }

        // online softmax in registers
        float tm1 = -INFINITY, tm2 = -INFINITY;
        #pragma unroll
        for (int nt = 0; nt < 8; nt++) {
            tm1 = fmaxf(tm1, fmaxf(sacc[nt][0], sacc[nt][1]));
            tm2 = fmaxf(tm2, fmaxf(sacc[nt][2], sacc[nt][3]));
        }
        tm1 = fmaxf(tm1, __shfl_xor_sync(0xffffffff, tm1, 1));
        tm1 = fmaxf(tm1, __shfl_xor_sync(0xffffffff, tm1, 2));
        tm2 = fmaxf(tm2, __shfl_xor_sync(0xffffffff, tm2, 1));
        tm2 = fmaxf(tm2, __shfl_xor_sync(0xffffffff, tm2, 2));
        float nm1 = fmaxf(m1, tm1), nm2 = fmaxf(m2, tm2);
        float sc1 = __expf(m1 - nm1), sc2 = __expf(m2 - nm2);

        float rs1 = 0.f, rs2 = 0.f;
        #pragma unroll
        for (int nt = 0; nt < 8; nt++) {
            float p0 = __expf(sacc[nt][0] - nm1);
            float p1 = __expf(sacc[nt][1] - nm1);
            float p2 = __expf(sacc[nt][2] - nm2);
            float p3 = __expf(sacc[nt][3] - nm2);
            rs1 += p0 + p1;
            rs2 += p2 + p3;
            *(float2*)&Ps[(wr + qm) * PSP + nt * 8 + 2 * qk] = make_float2(p0, p1);
            *(float2*)&Ps[(wr + qm + 8) * PSP + nt * 8 + 2 * qk] = make_float2(p2, p3);
        }
        rs1 += __shfl_xor_sync(0xffffffff, rs1, 1);
        rs1 += __shfl_xor_sync(0xffffffff, rs1, 2);
        rs2 += __shfl_xor_sync(0xffffffff, rs2, 1);
        rs2 += __shfl_xor_sync(0xffffffff, rs2, 2);
        l1 = l1 * sc1 + rs1;
        l2 = l2 * sc2 + rs2;
        m1 = nm1; m2 = nm2;

        #pragma unroll
        for (int nt = 0; nt < 8; nt++) {
            oacc[nt][0] *= sc1; oacc[nt][1] *= sc1;
            oacc[nt][2] *= sc2; oacc[nt][3] *= sc2;
        }
        __syncwarp();   // Ps rows are warp-private

        // O += P V
        #pragma unroll
        for (int ks = 0; ks < 8; ks++) {
            uint32_t af[4];
            af[0] = __float_as_uint(Ps[(wr + qm) * PSP + ks * 8 + qk]);
            af[1] = __float_as_uint(Ps[(wr + qm + 8) * PSP + ks * 8 + qk]);
            af[2] = __float_as_uint(Ps[(wr + qm) * PSP + ks * 8 + qk + 4]);
            af[3] = __float_as_uint(Ps[(wr + qm + 8) * PSP + ks * 8 + qk + 4]);
            #pragma unroll
            for (int nt = 0; nt < 8; nt++) {
                uint32_t b0 = __float_as_uint(Vc[(nt * 8 + qm) * VSP + ks * 8 + qk]);
                uint32_t b1 = __float_as_uint(Vc[(nt * 8 + qm) * VSP + ks * 8 + qk + 4]);
                mma_tf32_16x8x8(oacc[nt], af, b0, b1);
            }
        }
    }

    // epilogue: O/l -> g_att[b][t][c]
    float li1 = 1.f / l1, li2 = 1.f / l2;
    float* ob = g_att + (size_t)bb * TT * CC;
    int r1 = i0 + wr + qm, r2 = r1 + 8;
    int cb = hh * HD;
    #pragma unroll
    for (int nt = 0; nt < 8; nt++) {
        *(float2*)&ob[(size_t)r1 * CC + cb + nt * 8 + 2 * qk] =
            make_float2(oacc[nt][0] * li1, oacc[nt][1] * li1);
        *(float2*)&ob[(size_t)r2 * CC + cb + nt * 8 + 2 * qk] =
            make_float2(oacc[nt][2] * li2, oacc[nt][3] * li2);
    }
}

// ===========================================================================
extern "C" void kernel_launch(void* const* d_in, const int* in_sizes, int n_in,
                              void* d_out, int out_size) {
    const float* x      = (const float*)d_in[0];
    const float* gamma  = (const float*)d_in[1];
    const float* beta   = (const float*)d_in[2];
    const float* qkv_w  = (const float*)d_in[3];
    const float* qkv_b  = (const float*)d_in[4];
    const float* proj_w = (const float*)d_in[5];
    const float* proj_b = (const float*)d_in[6];
    float* out = (float*)d_out;

    float *xnt, *qkv, *att;
    cudaGetSymbolAddress((void**)&xnt, g_xnt);
    cudaGetSymbolAddress((void**)&qkv, g_qkv);
    cudaGetSymbolAddress((void**)&att, g_att);

    static int inited = 0;
    if (!inited) {
        cudaFuncSetAttribute(mma_gemm,
                             cudaFuncAttributeMaxDynamicSharedMemorySize,
                             GEMM_SMEM);
        cudaFuncSetAttribute(mma_attn,
                             cudaFuncAttributeMaxDynamicSharedMemorySize,
                             ATT_SMEM);
        inited = 1;
    }

    // 1. GroupNorm -> xn_t [b][t][c]
    gn_kernel<<<BB * NG, 256>>>(x, gamma, beta);

    // 2. QKV GEMM (tf32 mma.sync, cp.async): out [b][1536][t]
    mma_gemm<<<dim3(TT / 128, (3 * CC) / 128, BB), 256, GEMM_SMEM>>>(
        xnt, qkv_w, qkv_b, nullptr, qkv, 3 * CC);

    // 3. Flash attention (tf32 mma.sync, cp.async) -> g_att [b][t][c]
    mma_attn<<<dim3(TT / QT, NH, BB), 256, ATT_SMEM>>>();

    // 4. Proj GEMM (tf32 mma.sync, cp.async) + bias + residual -> d_out
    mma_gemm<<<dim3(TT / 128, CC / 128, BB), 256, GEMM_SMEM>>>(
        att, proj_w, proj_b, x, out, CC);
}